// round 7
// baseline (speedup 1.0000x reference)
#include <cuda_runtime.h>

#define BATCH 4096
#define TT    512
#define IN    20
#define HID   51
#define NG    204            // 4*HID
#define KDIM  71             // HID + IN
#define SPB   16
#define NBLK  (BATCH / SPB)  // 256
#define NTHR  512
#define NACT  408            // act threads: 2 gates x 4 seqs each

// float offsets in dynamic smem
#define OFF_W   0                     // w_t[71][204]: rows 0..50 = W_hh1^T, 51..70 = W_ih1^T
#define OFF_GT  (KDIM * NG)           // gates [204][20]
#define OFF_HX  (OFF_GT + NG * 20)    // hx [71][16]: rows 0..50 h, 51..70 x
#define OFF_W2  (OFF_HX + KDIM * 16)  // W_ih2 [4*51]
#define SMEM_FLOATS (OFF_W2 + NG)
#define SMEM_BYTES  (SMEM_FLOATS * 4) // ~79.8 KB -> 2 CTAs/SM

typedef unsigned long long ull;

__device__ __forceinline__ ull pack2(float v) {
    ull r; asm("mov.b64 %0, {%1, %1};" : "=l"(r) : "f"(v)); return r;
}
__device__ __forceinline__ ull fma2(ull a, ull b, ull c) {
    ull d; asm("fma.rn.f32x2 %0, %1, %2, %3;" : "=l"(d) : "l"(a), "l"(b), "l"(c)); return d;
}
__device__ __forceinline__ float fsig(float x)  { return __fdividef(1.0f, 1.0f + __expf(-x)); }
__device__ __forceinline__ float ftanh_(float x){ return 1.0f - __fdividef(2.0f, __expf(2.0f * x) + 1.0f); }

__global__ __launch_bounds__(NTHR, 2) void lstm_v7_kernel(
    const float* __restrict__ x,
    const float* __restrict__ W_ih1, const float* __restrict__ W_hh1,
    const float* __restrict__ b_ih1, const float* __restrict__ b_hh1,
    const float* __restrict__ W_ih2, const float* __restrict__ W_hh2,
    const float* __restrict__ b_ih2, const float* __restrict__ b_hh2,
    const float* __restrict__ W_mu,  const float* __restrict__ b_mu,
    const float* __restrict__ W_lv,  const float* __restrict__ b_lv,
    float* __restrict__ out)
{
    extern __shared__ float sm[];
    const int tid = threadIdx.x;
    const int b16 = blockIdx.x * SPB;

    // ---------------- init ----------------
    for (int i = tid; i < NG * HID; i += NTHR) {          // W_hh1^T -> rows 0..50
        int g = i / HID, k = i % HID;
        sm[OFF_W + k * NG + g] = W_hh1[i];
    }
    for (int i = tid; i < NG * IN; i += NTHR) {           // W_ih1^T -> rows 51..70
        int g = i / IN, j = i % IN;
        sm[OFF_W + (HID + j) * NG + g] = W_ih1[i];
    }
    for (int i = tid; i < HID * 16; i += NTHR)            // zero h rows
        sm[OFF_HX + i] = 0.f;
    if (tid < NG) sm[OFF_W2 + tid] = W_ih2[tid];          // [4][51]
    // x(0) -> hx rows 51..70 (16 threads, one seq each)
    if (tid >= 416 && tid < 416 + SPB) {
        int s = tid - 416;
        const float4* xp = reinterpret_cast<const float4*>(
            &x[((size_t)(b16 + s) * TT) * IN]);
        #pragma unroll
        for (int q = 0; q < 5; q++) {
            float4 v = xp[q];
            sm[OFF_HX + (HID + 4*q + 0) * 16 + s] = v.x;
            sm[OFF_HX + (HID + 4*q + 1) * 16 + s] = v.y;
            sm[OFF_HX + (HID + 4*q + 2) * 16 + s] = v.z;
            sm[OFF_HX + (HID + 4*q + 3) * 16 + s] = v.w;
        }
    }

    // act-thread mapping: gp = tid>>2 (gates 2gp, 2gp+1), sq4 = (tid&3)*4
    const int gp  = tid >> 2;
    const int sq4 = (tid & 3) << 2;
    ull bp0 = 0ULL, bp1 = 0ULL;
    if (tid < NACT) {
        bp0 = pack2(b_ih1[2*gp]     + b_hh1[2*gp]);
        bp1 = pack2(b_ih1[2*gp + 1] + b_hh1[2*gp + 1]);
    }
    // phase-1 cells: tid and tid+408
    const int u0 = tid >> 4,          s0 = tid & 15;
    const int u1 = (tid + NACT) >> 4, s1 = (tid + NACT) & 15;
    float c1a = 0.f, c1b = 0.f;

    // layer-2 threads: 448..463 (one per seq)
    const int l2s = tid - 448;
    float c2 = 0.f, h2 = 0.f, sum_h2 = 0.f;
    float l2b[4], l2w[4];
    if (tid >= 448 && l2s < SPB) {
        #pragma unroll
        for (int g = 0; g < 4; g++) { l2b[g] = b_ih2[g] + b_hh2[g]; l2w[g] = W_hh2[g]; }
    }
    __syncthreads();

    float4 xr[5];

    #pragma unroll 1
    for (int t = 0; t < TT; t++) {
        // ============ phase 0 ============
        if (tid < NACT) {
            // gates = bias + W * hx :  2 gates x 4 seqs, per k: 2 LDS + 2 pack + 4 FFMA2
            ull a00 = bp0, a01 = bp0, a10 = bp1, a11 = bp1;
            const float* wrow = &sm[OFF_W + 2 * gp];
            const float* hrow = &sm[OFF_HX + sq4];
            #pragma unroll
            for (int k = 0; k < KDIM; k++) {
                float2 wv = *reinterpret_cast<const float2*>(wrow + k * NG);
                ulonglong2 hv = *reinterpret_cast<const ulonglong2*>(hrow + k * 16);
                ull w0 = pack2(wv.x), w1 = pack2(wv.y);
                a00 = fma2(w0, hv.x, a00); a01 = fma2(w0, hv.y, a01);
                a10 = fma2(w1, hv.x, a10); a11 = fma2(w1, hv.y, a11);
            }
            *reinterpret_cast<ulonglong2*>(&sm[OFF_GT + (2*gp)     * 20 + sq4]) = make_ulonglong2(a00, a01);
            *reinterpret_cast<ulonglong2*>(&sm[OFF_GT + (2*gp + 1) * 20 + sq4]) = make_ulonglong2(a10, a11);
        } else if (tid >= 416 && tid < 416 + SPB) {
            if (t + 1 < TT) {                       // prefetch x(t+1) to regs
                int s = tid - 416;
                const float4* xp = reinterpret_cast<const float4*>(
                    &x[((size_t)(b16 + s) * TT + t + 1) * IN]);
                #pragma unroll
                for (int q = 0; q < 5; q++) xr[q] = xp[q];
            }
        } else if (tid >= 448 && l2s < SPB && t > 0) {
            // layer 2 consumes h(t-1)
            float zi = 0.f, zf = 0.f, zg = 0.f, zo = 0.f;
            #pragma unroll
            for (int k = 0; k < HID; k++) {
                float hv = sm[OFF_HX + k * 16 + l2s];
                zi += sm[OFF_W2 +         k] * hv;
                zf += sm[OFF_W2 + HID   + k] * hv;
                zg += sm[OFF_W2 + 2*HID + k] * hv;
                zo += sm[OFF_W2 + 3*HID + k] * hv;
            }
            float i2 = fsig  (zi + l2b[0] + l2w[0] * h2);
            float f2 = fsig  (zf + l2b[1] + l2w[1] * h2);
            float g2v= ftanh_(zg + l2b[2] + l2w[2] * h2);
            float o2 = fsig  (zo + l2b[3] + l2w[3] * h2);
            c2 = f2 * c2 + i2 * g2v;
            h2 = o2 * ftanh_(c2);
            sum_h2 += h2;
        }
        __syncthreads();

        // ============ phase 1 ============
        if (tid < NACT) {
            // two cells per thread
            {
                float gi = sm[OFF_GT + (u0)         * 20 + s0];
                float gf = sm[OFF_GT + (HID + u0)   * 20 + s0];
                float gg = sm[OFF_GT + (2*HID + u0) * 20 + s0];
                float go = sm[OFF_GT + (3*HID + u0) * 20 + s0];
                c1a = fsig(gf) * c1a + fsig(gi) * ftanh_(gg);
                sm[OFF_HX + u0 * 16 + s0] = fsig(go) * ftanh_(c1a);
            }
            {
                float gi = sm[OFF_GT + (u1)         * 20 + s1];
                float gf = sm[OFF_GT + (HID + u1)   * 20 + s1];
                float gg = sm[OFF_GT + (2*HID + u1) * 20 + s1];
                float go = sm[OFF_GT + (3*HID + u1) * 20 + s1];
                c1b = fsig(gf) * c1b + fsig(gi) * ftanh_(gg);
                sm[OFF_HX + u1 * 16 + s1] = fsig(go) * ftanh_(c1b);
            }
        } else if (tid >= 416 && tid < 416 + SPB) {
            if (t + 1 < TT) {                        // x(t+1) -> hx rows 51..70
                int s = tid - 416;
                #pragma unroll
                for (int q = 0; q < 5; q++) {
                    sm[OFF_HX + (HID + 4*q + 0) * 16 + s] = xr[q].x;
                    sm[OFF_HX + (HID + 4*q + 1) * 16 + s] = xr[q].y;
                    sm[OFF_HX + (HID + 4*q + 2) * 16 + s] = xr[q].z;
                    sm[OFF_HX + (HID + 4*q + 3) * 16 + s] = xr[q].w;
                }
            }
        }
        __syncthreads();
    }

    // ---------- final layer-2 step (h(T-1)) + epilogue ----------
    if (tid >= 448 && l2s < SPB) {
        float zi = 0.f, zf = 0.f, zg = 0.f, zo = 0.f;
        #pragma unroll
        for (int k = 0; k < HID; k++) {
            float hv = sm[OFF_HX + k * 16 + l2s];
            zi += sm[OFF_W2 +         k] * hv;
            zf += sm[OFF_W2 + HID   + k] * hv;
            zg += sm[OFF_W2 + 2*HID + k] * hv;
            zo += sm[OFF_W2 + 3*HID + k] * hv;
        }
        float i2 = fsig  (zi + l2b[0] + l2w[0] * h2);
        float f2 = fsig  (zf + l2b[1] + l2w[1] * h2);
        float g2v= ftanh_(zg + l2b[2] + l2w[2] * h2);
        float o2 = fsig  (zo + l2b[3] + l2w[3] * h2);
        c2 = f2 * c2 + i2 * g2v;
        h2 = o2 * ftanh_(c2);
        sum_h2 += h2;

        float agg = sum_h2 * (1.0f / TT);
        float mu  = W_mu[0] * agg + b_mu[0];
        float lv  = W_lv[0] * agg + b_lv[0];
        float sg  = __expf(0.5f * lv);
        int b = b16 + l2s;
        out[b]           = mu - 1.96f * sg;
        out[BATCH + b]   = mu;
        out[2*BATCH + b] = mu + 1.96f * sg;
        out[3*BATCH + b] = lv;
    }
}

extern "C" void kernel_launch(void* const* d_in, const int* in_sizes, int n_in,
                              void* d_out, int out_size) {
    const float* x     = (const float*)d_in[0];
    const float* W_ih1 = (const float*)d_in[1];
    const float* W_hh1 = (const float*)d_in[2];
    const float* b_ih1 = (const float*)d_in[3];
    const float* b_hh1 = (const float*)d_in[4];
    const float* W_ih2 = (const float*)d_in[5];
    const float* W_hh2 = (const float*)d_in[6];
    const float* b_ih2 = (const float*)d_in[7];
    const float* b_hh2 = (const float*)d_in[8];
    const float* W_mu  = (const float*)d_in[9];
    const float* b_mu  = (const float*)d_in[10];
    const float* W_lv  = (const float*)d_in[11];
    const float* b_lv  = (const float*)d_in[12];
    float* out = (float*)d_out;

    cudaFuncSetAttribute(lstm_v7_kernel,
                         cudaFuncAttributeMaxDynamicSharedMemorySize, SMEM_BYTES);
    lstm_v7_kernel<<<NBLK, NTHR, SMEM_BYTES>>>(x, W_ih1, W_hh1, b_ih1, b_hh1,
                                               W_ih2, W_hh2, b_ih2, b_hh2,
                                               W_mu, b_mu, W_lv, b_lv, out);
}

// round 8
// speedup vs baseline: 1.4389x; 1.4389x over previous
#include <cuda_runtime.h>

#define BATCH 4096
#define TT    512
#define IN    20
#define HID   51
#define NG    204
#define KDIM  71              // HID + IN
#define UPAD  64              // units padded to 64
#define WROW  (UPAD * 4)      // 256 floats per k-row
#define SPB   16
#define NBLK  (BATCH / SPB)   // 256
#define NTHR  160             // 128 matmul + 32 helper (16 used)

// float offsets in dynamic smem
#define OFF_W   0                         // w_il[71][256]: [k][u*4+g]
#define OFF_HX  (KDIM * WROW)             // two buffers [2][71][16]; rows 0..50 h, 51..70 x
#define HXBUF   (KDIM * 16)               // 1136 floats
#define OFF_W2  (OFF_HX + 2 * HXBUF)      // W_ih2 [4][51]
#define SMEM_FLOATS (OFF_W2 + NG)
#define SMEM_BYTES  (SMEM_FLOATS * 4)     // ~82.6 KB -> 2 CTAs/SM

typedef unsigned long long ull;

__device__ __forceinline__ ull pack2(float v) {
    ull r; asm("mov.b64 %0, {%1, %1};" : "=l"(r) : "f"(v)); return r;
}
__device__ __forceinline__ ull fma2(ull a, ull b, ull c) {
    ull d; asm("fma.rn.f32x2 %0, %1, %2, %3;" : "=l"(d) : "l"(a), "l"(b), "l"(c)); return d;
}
__device__ __forceinline__ void unpack2(ull v, float& lo, float& hi) {
    asm("mov.b64 {%0, %1}, %2;" : "=f"(lo), "=f"(hi) : "l"(v));
}
__device__ __forceinline__ float fsig(float x)  { return __fdividef(1.0f, 1.0f + __expf(-x)); }
__device__ __forceinline__ float ftanh_(float x){ return 1.0f - __fdividef(2.0f, __expf(2.0f * x) + 1.0f); }

__global__ __launch_bounds__(NTHR, 2) void lstm_v8_kernel(
    const float* __restrict__ x,
    const float* __restrict__ W_ih1, const float* __restrict__ W_hh1,
    const float* __restrict__ b_ih1, const float* __restrict__ b_hh1,
    const float* __restrict__ W_ih2, const float* __restrict__ W_hh2,
    const float* __restrict__ b_ih2, const float* __restrict__ b_hh2,
    const float* __restrict__ W_mu,  const float* __restrict__ b_mu,
    const float* __restrict__ W_lv,  const float* __restrict__ b_lv,
    float* __restrict__ out)
{
    extern __shared__ float sm[];
    const int tid = threadIdx.x;
    const int b16 = blockIdx.x * SPB;

    // ---------------- init ----------------
    // interleaved transpose: w_il[k][u*4+g], gate order g = i,f,g,o (G = g*51+u)
    for (int i = tid; i < KDIM * WROW; i += NTHR) {
        int k = i >> 8, j = i & 255;
        int u = j >> 2, g = j & 3;
        float v = 0.f;
        if (u < HID) {
            int G = g * HID + u;
            v = (k < HID) ? W_hh1[G * HID + k] : W_ih1[G * IN + (k - HID)];
        }
        sm[OFF_W + i] = v;
    }
    for (int i = tid; i < HID * 16; i += NTHR) sm[OFF_HX + i] = 0.f;   // h rows buf0
    for (int i = tid; i < NG; i += NTHR) sm[OFF_W2 + i] = W_ih2[i];
    if (tid < SPB) {   // x(0) -> buf0 rows 51..70
        const float4* xp = reinterpret_cast<const float4*>(&x[((size_t)(b16 + tid) * TT) * IN]);
        #pragma unroll
        for (int q = 0; q < 5; q++) {
            float4 v = xp[q];
            sm[OFF_HX + (HID + 4*q + 0) * 16 + tid] = v.x;
            sm[OFF_HX + (HID + 4*q + 1) * 16 + tid] = v.y;
            sm[OFF_HX + (HID + 4*q + 2) * 16 + tid] = v.z;
            sm[OFF_HX + (HID + 4*q + 3) * 16 + tid] = v.w;
        }
    }

    // matmul threads 0..127: unit u = tid>>1, seq-half sh8 = (tid&1)*8
    const int u   = tid >> 1;
    const int sh8 = (tid & 1) << 3;
    ull bp[4] = {0ULL, 0ULL, 0ULL, 0ULL};
    if (tid < 128 && u < HID) {
        #pragma unroll
        for (int g = 0; g < 4; g++)
            bp[g] = pack2(b_ih1[g * HID + u] + b_hh1[g * HID + u]);
    }
    float c1[8] = {0.f,0.f,0.f,0.f,0.f,0.f,0.f,0.f};

    // helper threads 128..143: seq hs; x prefetch + layer 2
    const int hs = tid - 128;
    float c2 = 0.f, h2 = 0.f, sum_h2 = 0.f;
    float l2b[4] = {0,0,0,0}, l2w[4] = {0,0,0,0};
    if (hs >= 0 && hs < SPB) {
        #pragma unroll
        for (int g = 0; g < 4; g++) { l2b[g] = b_ih2[g] + b_hh2[g]; l2w[g] = W_hh2[g]; }
    }
    __syncthreads();

    #pragma unroll 1
    for (int t = 0; t < TT; t++) {
        const float* A = &sm[OFF_HX + (t & 1) * HXBUF];          // h(t-1), x(t)
        float*       B = &sm[OFF_HX + ((t + 1) & 1) * HXBUF];    // h(t), x(t+1)

        if (tid < 128) {
            // ---- gates for unit u, 8 seqs, all 4 gates in registers ----
            ull a[16];   // a[g*4+p], p -> seqs (2p, 2p+1)
            #pragma unroll
            for (int g = 0; g < 4; g++) {
                a[g*4+0] = bp[g]; a[g*4+1] = bp[g]; a[g*4+2] = bp[g]; a[g*4+3] = bp[g];
            }
            const float* wb = &sm[OFF_W + u * 4];
            const float* hb = A + sh8;
            #pragma unroll
            for (int k = 0; k < KDIM; k++) {
                float4 w4 = *reinterpret_cast<const float4*>(wb + k * WROW);
                ulonglong2 h0 = *reinterpret_cast<const ulonglong2*>(hb + k * 16);
                ulonglong2 h1 = *reinterpret_cast<const ulonglong2*>(hb + k * 16 + 4);
                ull wi = pack2(w4.x), wf = pack2(w4.y), wg = pack2(w4.z), wo = pack2(w4.w);
                a[0]  = fma2(wi, h0.x, a[0]);  a[1]  = fma2(wi, h0.y, a[1]);
                a[2]  = fma2(wi, h1.x, a[2]);  a[3]  = fma2(wi, h1.y, a[3]);
                a[4]  = fma2(wf, h0.x, a[4]);  a[5]  = fma2(wf, h0.y, a[5]);
                a[6]  = fma2(wf, h1.x, a[6]);  a[7]  = fma2(wf, h1.y, a[7]);
                a[8]  = fma2(wg, h0.x, a[8]);  a[9]  = fma2(wg, h0.y, a[9]);
                a[10] = fma2(wg, h1.x, a[10]); a[11] = fma2(wg, h1.y, a[11]);
                a[12] = fma2(wo, h0.x, a[12]); a[13] = fma2(wo, h0.y, a[13]);
                a[14] = fma2(wo, h1.x, a[14]); a[15] = fma2(wo, h1.y, a[15]);
            }
            // ---- in-register activations, write h(t) to B ----
            if (u < HID) {
                float hv[8];
                #pragma unroll
                for (int p = 0; p < 4; p++) {
                    float i0,i1,f0,f1,g0,g1,o0,o1;
                    unpack2(a[p],      i0, i1);
                    unpack2(a[4 + p],  f0, f1);
                    unpack2(a[8 + p],  g0, g1);
                    unpack2(a[12 + p], o0, o1);
                    float ca = fsig(f0) * c1[2*p]     + fsig(i0) * ftanh_(g0);
                    c1[2*p] = ca;     hv[2*p]     = fsig(o0) * ftanh_(ca);
                    float cb = fsig(f1) * c1[2*p + 1] + fsig(i1) * ftanh_(g1);
                    c1[2*p+1] = cb;   hv[2*p + 1] = fsig(o1) * ftanh_(cb);
                }
                *reinterpret_cast<float4*>(B + u * 16 + sh8)     = make_float4(hv[0], hv[1], hv[2], hv[3]);
                *reinterpret_cast<float4*>(B + u * 16 + sh8 + 4) = make_float4(hv[4], hv[5], hv[6], hv[7]);
            }
        } else if (hs < SPB) {
            // fire x(t+1) loads early
            float4 xv[5];
            if (t + 1 < TT) {
                const float4* xp = reinterpret_cast<const float4*>(
                    &x[((size_t)(b16 + hs) * TT + t + 1) * IN]);
                #pragma unroll
                for (int q = 0; q < 5; q++) xv[q] = xp[q];
            }
            // layer 2 on h(t-1) in A
            if (t > 0) {
                float zi = 0.f, zf = 0.f, zg = 0.f, zo = 0.f;
                #pragma unroll
                for (int k = 0; k < HID; k++) {
                    float hvv = A[k * 16 + hs];
                    zi += sm[OFF_W2 +          k] * hvv;
                    zf += sm[OFF_W2 + HID    + k] * hvv;
                    zg += sm[OFF_W2 + 2*HID  + k] * hvv;
                    zo += sm[OFF_W2 + 3*HID  + k] * hvv;
                }
                float i2 = fsig  (zi + l2b[0] + l2w[0] * h2);
                float f2 = fsig  (zf + l2b[1] + l2w[1] * h2);
                float g2v= ftanh_(zg + l2b[2] + l2w[2] * h2);
                float o2 = fsig  (zo + l2b[3] + l2w[3] * h2);
                c2 = f2 * c2 + i2 * g2v;
                h2 = o2 * ftanh_(c2);
                sum_h2 += h2;
            }
            // store x(t+1) into B rows 51..70
            if (t + 1 < TT) {
                #pragma unroll
                for (int q = 0; q < 5; q++) {
                    B[(HID + 4*q + 0) * 16 + hs] = xv[q].x;
                    B[(HID + 4*q + 1) * 16 + hs] = xv[q].y;
                    B[(HID + 4*q + 2) * 16 + hs] = xv[q].z;
                    B[(HID + 4*q + 3) * 16 + hs] = xv[q].w;
                }
            }
        }
        __syncthreads();
    }

    // ---------- final layer-2 step on h(T-1) + epilogue ----------
    if (hs >= 0 && hs < SPB) {
        const float* A = &sm[OFF_HX + (TT & 1) * HXBUF];
        float zi = 0.f, zf = 0.f, zg = 0.f, zo = 0.f;
        #pragma unroll
        for (int k = 0; k < HID; k++) {
            float hvv = A[k * 16 + hs];
            zi += sm[OFF_W2 +          k] * hvv;
            zf += sm[OFF_W2 + HID    + k] * hvv;
            zg += sm[OFF_W2 + 2*HID  + k] * hvv;
            zo += sm[OFF_W2 + 3*HID  + k] * hvv;
        }
        float i2 = fsig  (zi + l2b[0] + l2w[0] * h2);
        float f2 = fsig  (zf + l2b[1] + l2w[1] * h2);
        float g2v= ftanh_(zg + l2b[2] + l2w[2] * h2);
        float o2 = fsig  (zo + l2b[3] + l2w[3] * h2);
        c2 = f2 * c2 + i2 * g2v;
        h2 = o2 * ftanh_(c2);
        sum_h2 += h2;

        float agg = sum_h2 * (1.0f / TT);
        float mu  = W_mu[0] * agg + b_mu[0];
        float lv  = W_lv[0] * agg + b_lv[0];
        float sg  = __expf(0.5f * lv);
        int b = b16 + hs;
        out[b]           = mu - 1.96f * sg;
        out[BATCH + b]   = mu;
        out[2*BATCH + b] = mu + 1.96f * sg;
        out[3*BATCH + b] = lv;
    }
}

extern "C" void kernel_launch(void* const* d_in, const int* in_sizes, int n_in,
                              void* d_out, int out_size) {
    const float* x     = (const float*)d_in[0];
    const float* W_ih1 = (const float*)d_in[1];
    const float* W_hh1 = (const float*)d_in[2];
    const float* b_ih1 = (const float*)d_in[3];
    const float* b_hh1 = (const float*)d_in[4];
    const float* W_ih2 = (const float*)d_in[5];
    const float* W_hh2 = (const float*)d_in[6];
    const float* b_ih2 = (const float*)d_in[7];
    const float* b_hh2 = (const float*)d_in[8];
    const float* W_mu  = (const float*)d_in[9];
    const float* b_mu  = (const float*)d_in[10];
    const float* W_lv  = (const float*)d_in[11];
    const float* b_lv  = (const float*)d_in[12];
    float* out = (float*)d_out;

    cudaFuncSetAttribute(lstm_v8_kernel,
                         cudaFuncAttributeMaxDynamicSharedMemorySize, SMEM_BYTES);
    lstm_v8_kernel<<<NBLK, NTHR, SMEM_BYTES>>>(x, W_ih1, W_hh1, b_ih1, b_hh1,
                                               W_ih2, W_hh2, b_ih2, b_hh2,
                                               W_mu, b_mu, W_lv, b_lv, out);
}